// round 11
// baseline (speedup 1.0000x reference)
#include <cuda_runtime.h>

// MixedActivation: cols with (col % 6) < 3 -> x*x ; else PReLU with slope
// prelu_a[(col % 6) - 3]. x is [1000000, 48] fp32, contiguous.
//
// R11: last untested variable — TEMPORAL load/store interleave. All prior
// variants front-batched loads then burst stores (RRR->WWW per thread).
// This version software-pipelines: prefetch v[k+1], then compute+store v[k],
// presenting the memory controller a smoother R/W cadence. Everything else
// identical to the locked-in best (R6/R10: 53.06us kernel / 61.44us bench,
// exact grid 15625, zero predicates, .cs both sides).
//
// Phase logic: float4 index i covers cols 4i..4i+3; (4i) mod 6 depends only
// on r = i % 3: r=0 -> mods {0,1,2,3}, r=1 -> {4,5,0,1}, r=2 -> {2,3,4,5}.

#define UNROLL 3
#define TPB 256

__device__ __forceinline__ float4 apply_act(float4 v, int i,
                                            float a0, float a1, float a2) {
    int r = i % 3;
    int m0 = r * 4;
    float x[4] = {v.x, v.y, v.z, v.w};
    float o[4];
#pragma unroll
    for (int c = 0; c < 4; c++) {
        int m = m0 + c;
        if (m >= 6) m -= 6;                       // m = col % 6 (0..5)
        float a = (m == 3) ? a0 : ((m == 4) ? a1 : a2);
        float sq = x[c] * x[c];
        float pr = fmaxf(x[c], 0.0f) + a * fminf(x[c], 0.0f);
        o[c] = (m < 3) ? sq : pr;                 // predicated select
    }
    return make_float4(o[0], o[1], o[2], o[3]);
}

__global__ void __launch_bounds__(TPB)
mixed_act_kernel(const float4* __restrict__ in,
                 const float* __restrict__ pa,
                 float4* __restrict__ out) {
    const int base = blockIdx.x * (TPB * UNROLL) + threadIdx.x;

    const float a0 = __ldg(pa + 0);
    const float a1 = __ldg(pa + 1);
    const float a2 = __ldg(pa + 2);

    // Rolling pipeline: prefetch next tile before storing current one.
    float4 cur = __ldcs(&in[base]);
#pragma unroll
    for (int k = 0; k < UNROLL; k++) {
        float4 nxt;
        if (k + 1 < UNROLL)
            nxt = __ldcs(&in[base + (k + 1) * TPB]);   // load k+1 in flight

        const int i = base + k * TPB;
        __stcs(&out[i], apply_act(cur, i, a0, a1, a2)); // store k

        cur = nxt;
    }
}

extern "C" void kernel_launch(void* const* d_in, const int* in_sizes, int n_in,
                              void* d_out, int out_size) {
    const float* x  = (const float*)d_in[0];
    const float* pa = (const float*)d_in[1];
    float* out = (float*)d_out;

    int n4 = out_size / 4;                   // 12,000,000 float4s
    int blocks = n4 / (TPB * UNROLL);        // exactly 15625
    mixed_act_kernel<<<blocks, TPB>>>((const float4*)x, pa, (float4*)out);
}